// round 16
// baseline (speedup 1.0000x reference)
#include <cuda_runtime.h>
#include <math_constants.h>

#define N_G      1500
#define CHUNKS   9
#define GPC      168                 // gaussians per chunk
#define PPC      84                  // pairs per chunk
#define N_G_PAD  (CHUNKS * GPC)      // 1512
#define HDIM     256
#define OUT_ELEMS (HDIM * HDIM * 3)
#define NBLK     (CHUNKS * 32)       // 288 blocks; <= 296 residency slots at occ 2
#define ROWBLKS  32
#define BIAS     110.0f
#define UNSAFE_T 160.0f

__device__ float        g_part[(CHUNKS - 1) * OUT_ELEMS];
__device__ unsigned int g_qmax_bits = 0xFF800000u;  // -inf; RED.MIN-on-bits == float max (q<=0)
__device__ unsigned int g_qcnt  = 0;                // scan arrivals; atomicInc wraps -> replay-safe
__device__ unsigned int g_qflag = 0;                // monotonic release epoch
__device__ unsigned int g_rbcnt[ROWBLKS];           // per-rowblock arrivals; wraps -> replay-safe

typedef unsigned long long u64;

__device__ __forceinline__ u64 f2add(u64 a, u64 b) {
    u64 r; asm("add.rn.f32x2 %0, %1, %2;" : "=l"(r) : "l"(a), "l"(b)); return r;
}
__device__ __forceinline__ u64 f2mul(u64 a, u64 b) {
    u64 r; asm("mul.rn.f32x2 %0, %1, %2;" : "=l"(r) : "l"(a), "l"(b)); return r;
}
__device__ __forceinline__ u64 f2fma(u64 a, u64 b, u64 c) {
    u64 r; asm("fma.rn.f32x2 %0, %1, %2, %3;" : "=l"(r) : "l"(a), "l"(b), "l"(c)); return r;
}
__device__ __forceinline__ u64 f2pack(float lo, float hi) {
    u64 r; asm("mov.b64 %0, {%1, %2};" : "=l"(r) : "f"(lo), "f"(hi)); return r;
}
__device__ __forceinline__ void f2unpack(u64 v, float& lo, float& hi) {
    asm("mov.b64 {%0, %1}, %2;" : "=f"(lo), "=f"(hi) : "l"(v));
}
__device__ __forceinline__ u64 f2ex2(u64 q) {
    float a, b; f2unpack(q, a, b);
    float wa, wb;
    asm("ex2.approx.ftz.f32 %0, %1;" : "=f"(wa) : "f"(a));
    asm("ex2.approx.ftz.f32 %0, %1;" : "=f"(wb) : "f"(b));
    return f2pack(wa, wb);
}
__device__ __forceinline__ float fast_tanh(float x) {
    float e = __expf(2.0f * x);
    return (e - 1.0f) * __frcp_rn(e + 1.0f);
}
__device__ __forceinline__ float fast_sigmoid(float x) {
    return __frcp_rn(1.0f + __expf(-x));
}

// ONE kernel, NO global barrier. 288 blocks = 9 chunks x 32 rowblocks; 256 thr.
// Phases: prep -> safe-first permutation -> qmax partial + qcnt release ->
// render -> per-rowblock last-writer finish (9th arriving chunk-block of a
// rowblock finishes its 8 rows; others exit).
__global__ void __launch_bounds__(256, 2) splat_kernel(
    float* __restrict__ out,
    const float* __restrict__ mean, const float* __restrict__ alpha,
    const float* __restrict__ scale, const float* __restrict__ theta,
    const float* __restrict__ rgb)
{
    __shared__ __align__(16) float tmp[PPC * 24];
    __shared__ __align__(16) float sp[PPC * 24];
    __shared__ float          sflagg[GPC];
    __shared__ int            sperm[PPC];
    __shared__ int            snsafe;
    __shared__ unsigned int   smy_epoch;
    __shared__ unsigned int   slast;

    int tid    = threadIdx.x;
    int chunk  = blockIdx.x >> 5;
    int rowblk = blockIdx.x & 31;

    if (tid == 0) smy_epoch = *(volatile unsigned int*)&g_qflag;  // snapshot BEFORE our qcnt arrival

    const float TWO_PI = 6.283185307179586f;
    const float K      = -0.7213475204444817f;   // -0.5*log2(e)
    const float STEP   = 2.0f / 255.0f;
    const float H      = 6.0f / 255.0f;

    // ---- in-block prep: this chunk's 168 gaussian params -> TEMP ----
    if (tid < GPC) {
        int g = chunk * GPC + tid;

        float A, B, C, mx, my, cr = 0.f, cg = 0.f, cb = 0.f;
        if (g < N_G) {
            float ang = fast_sigmoid(theta[g]) * TWO_PI;
            float s = __sinf(ang), c = __cosf(ang);
            float sx = scale[g * 2 + 0], sy = scale[g * 2 + 1];
            float sx2 = sx * sx, sy2 = sy * sy;

            float cov00 = c * c * sx2 + s * s * sy2 + 1e-6f;
            float cov01 = c * s * (sx2 - sy2);
            float cov11 = s * s * sx2 + c * c * sy2 + 1e-6f;

            float idet = __frcp_rn(cov00 * cov11 - cov01 * cov01);
            A = K * ( cov11 * idet);
            B = 2.0f * K * (-cov01 * idet);
            C = K * ( cov00 * idet);

            mx = fast_tanh(mean[g * 2 + 0]) * 3.0f;
            my = fast_tanh(mean[g * 2 + 1]) * 3.0f;

            float al = fast_sigmoid(alpha[g]);
            cr = (fast_tanh(rgb[g * 3 + 0]) * 2.0f + 1.0f) * 0.5f * al;
            cg = (fast_tanh(rgb[g * 3 + 1]) * 2.0f + 1.0f) * 0.5f * al;
            cb = (fast_tanh(rgb[g * 3 + 2]) * 2.0f + 1.0f) * 0.5f * al;
        } else {
            A = -1.f; B = 0.f; C = -1.f; mx = 0.f; my = 0.f;   // benign pad, zero color
        }

        int j = tid >> 1, o = tid & 1;
        float* p = &tmp[j * 24 + o];
        p[0]  = A;  p[2]  = B;  p[4]  = C;
        p[6]  = -mx; p[8] = -my;
        p[10] = 2.0f * A * H;              // P
        p[12] = A * H * H;                 // Q
        p[14] = B * H;                     // R
        p[16] = cr; p[18] = cg; p[20] = cb;
        p[22] = exp2f(2.0f * A * H * H);   // rho (A<0 -> <=1, finite)
        sflagg[tid] = (2.0f * fabsf(A) + fabsf(B) >= UNSAFE_T) ? 1.0f : 0.0f;
    }
    __syncthreads();

    // ---- deterministic safe-first permutation (thread 0, serial) ----
    if (tid == 0) {
        int ns = 0;
        for (int j = 0; j < PPC; j++)
            if (sflagg[2 * j] == 0.f && sflagg[2 * j + 1] == 0.f) ns++;
        int si = 0, ui = ns;
        for (int j = 0; j < PPC; j++) {
            bool safe = (sflagg[2 * j] == 0.f && sflagg[2 * j + 1] == 0.f);
            sperm[j] = safe ? si++ : ui++;
        }
        snsafe = ns;
    }
    __syncthreads();

    // ---- permute-copy TEMP -> SP ----
    {
        const u64* src = (const u64*)tmp;
        u64* dst = (u64*)sp;
        for (int i = tid; i < PPC * 12; i += 256) {
            int j = i / 12, w = i - j * 12;
            dst[sperm[j] * 12 + w] = src[i];
        }
    }
    __syncthreads();

    int warp = tid >> 5, lane = tid & 31;
    int row  = rowblk * 8 + warp;
    int x0i  = lane * 8;

    float py = (row * STEP - 1.0f) * 3.0f;
    float px = (x0i * STEP - 1.0f) * 3.0f;
    u64 py2   = f2pack(py, py);
    u64 px2   = f2pack(px, px);
    u64 BIAS2 = f2pack(BIAS, BIAS);
    int nsafe = snsafe;

    // ---- qmax partial: exact lattice row-max (TEMP order, pad-guarded) ----
    {
        float qbest = -CUDART_INF_F;
        #pragma unroll
        for (int i = lane; i < GPC; i += 32) {
            int g = chunk * GPC + i;
            if (g < N_G) {
                int j = i >> 1, o = i & 1;
                float A  = tmp[j * 24 + o + 0];
                float B  = tmp[j * 24 + o + 2];
                float Cc = tmp[j * 24 + o + 4];
                float mx = -tmp[j * 24 + o + 6];
                float my = -tmp[j * 24 + o + 8];
                float dy = py - my;
                float ct = Cc * dy * dy;
                float bd = B * dy;
                float xs = -B * 0.5f * __frcp_rn(A) * dy;      // continuous argmax
                float tt = fmaf(xs, 42.5f, 127.5f);
                float i0f = fminf(fmaxf(floorf(tt), 0.0f), 255.0f);
                float i1f = fminf(i0f + 1.0f, 255.0f);
                float x0 = (i0f * STEP - 1.0f) * 3.0f;
                float x1 = (i1f * STEP - 1.0f) * 3.0f;
                float d0 = x0 - mx, d1 = x1 - mx;
                float q0 = fmaf(fmaf(A, d0, bd), d0, ct);
                float q1 = fmaf(fmaf(A, d1, bd), d1, ct);
                qbest = fmaxf(qbest, fmaxf(q0, q1));
            }
        }
        #pragma unroll
        for (int off = 16; off > 0; off >>= 1)
            qbest = fmaxf(qbest, __shfl_xor_sync(0xFFFFFFFFu, qbest, off));
        if (lane == 0)
            atomicMin(&g_qmax_bits, __float_as_uint(qbest));
    }

    // all 8 warps' qmax contributions posted -> count this block's scan arrival
    __syncthreads();
    if (tid == 0) {
        __threadfence();
        unsigned int old = atomicInc(&g_qcnt, NBLK - 1);   // 288th wraps to 0
        if (old == NBLK - 1)
            atomicAdd(&g_qflag, 1);                        // release epoch (monotonic)
    }

    // ---- render: two uniform loops, lane owns 8 contiguous px ----
    u64 racc[8], gacc[8], bacc[8];
    #pragma unroll
    for (int k = 0; k < 8; k++) { racc[k] = 0ull; gacc[k] = 0ull; bacc[k] = 0ull; }

    const ulonglong2* spp = (const ulonglong2*)sp;

    // safe pairs: geometric recurrence (4 ex2 / pair-iter)
    for (int j = 0; j < nsafe; j++) {
        ulonglong2 p0 = spp[j * 6 + 0];  // {A, B}
        ulonglong2 p1 = spp[j * 6 + 1];  // {C, nmx}
        ulonglong2 p2 = spp[j * 6 + 2];  // {nmy, P}
        ulonglong2 p3 = spp[j * 6 + 3];  // {Q, R}
        ulonglong2 p4 = spp[j * 6 + 4];  // {cr, cg}
        ulonglong2 p5 = spp[j * 6 + 5];  // {cb, rho}

        u64 dy   = f2add(py2, p2.x);
        u64 dyq  = f2mul(dy, dy);
        u64 bdy  = f2mul(p0.y, dy);
        u64 cdyb = f2fma(p1.x, dyq, BIAS2);                  // C*dy^2 + BIAS
        u64 dx0  = f2add(px2, p1.y);
        u64 q0   = f2fma(f2fma(p0.x, dx0, bdy), dx0, cdyb);
        u64 e0   = f2fma(p2.y, dx0, f2fma(p3.y, dy, p3.x));  // P*dx0 + R*dy + Q

        u64 w = f2ex2(q0);
        u64 r = f2ex2(e0);
        #pragma unroll
        for (int k = 0; k < 8; k++) {
            racc[k] = f2fma(w, p4.x, racc[k]);
            gacc[k] = f2fma(w, p4.y, gacc[k]);
            bacc[k] = f2fma(w, p5.x, bacc[k]);
            w = f2mul(w, r);
            r = f2mul(r, p5.y);
        }
    }

    // unsafe pairs: additive-q chain (per-px ex2; flush-immune)
    for (int j = nsafe; j < PPC; j++) {
        ulonglong2 p0 = spp[j * 6 + 0];
        ulonglong2 p1 = spp[j * 6 + 1];
        ulonglong2 p2 = spp[j * 6 + 2];
        ulonglong2 p3 = spp[j * 6 + 3];
        ulonglong2 p4 = spp[j * 6 + 4];
        ulonglong2 p5 = spp[j * 6 + 5];

        u64 dy   = f2add(py2, p2.x);
        u64 dyq  = f2mul(dy, dy);
        u64 bdy  = f2mul(p0.y, dy);
        u64 cdyb = f2fma(p1.x, dyq, BIAS2);
        u64 dx0  = f2add(px2, p1.y);
        u64 q    = f2fma(f2fma(p0.x, dx0, bdy), dx0, cdyb);
        u64 e    = f2fma(p2.y, dx0, f2fma(p3.y, dy, p3.x));
        u64 t2   = f2add(p3.x, p3.x);                        // 2*A*h^2

        #pragma unroll
        for (int k = 0; k < 8; k++) {
            u64 w = f2ex2(q);
            racc[k] = f2fma(w, p4.x, racc[k]);
            gacc[k] = f2fma(w, p4.y, gacc[k]);
            bacc[k] = f2fma(w, p5.x, bacc[k]);
            q = f2add(q, e);
            e = f2add(e, t2);
        }
    }

    {
        float* dst = (chunk == 0) ? out : (g_part + (chunk - 1) * OUT_ELEMS);
        float* o = &dst[(row * HDIM + x0i) * 3];
        #pragma unroll
        for (int k = 0; k < 8; k++) {
            float t0, t1;
            f2unpack(racc[k], t0, t1); o[k * 3 + 0] = t0 + t1;
            f2unpack(gacc[k], t0, t1); o[k * 3 + 1] = t0 + t1;
            f2unpack(bacc[k], t0, t1); o[k * 3 + 2] = t0 + t1;
        }
    }

    // ---- last-writer election for this rowblock ----
    __syncthreads();
    if (tid == 0) {
        __threadfence();                                   // publish this block's stream
        slast = atomicInc(&g_rbcnt[rowblk], CHUNKS - 1);   // 9th sees old==8; wraps to 0
    }
    __syncthreads();
    if (slast != CHUNKS - 1) return;                       // not the last writer -> done

    // ---- finisher: wait for qmax release (provably ~already done), then finish 8 rows ----
    if (tid == 0) {
        while (*(volatile unsigned int*)&g_qflag == smy_epoch)
            __nanosleep(64);
    }
    __syncthreads();
    __threadfence();                                       // acquire other blocks' streams

    {
        float qmax = __uint_as_float(*(volatile unsigned int*)&g_qmax_bits);
        float scl  = exp2f(-qmax - BIAS);                  // un-bias + 1/max(splat)
        int base = rowblk * 8 * HDIM * 3;                  // 6144 elements
        for (int i = tid; i < 8 * HDIM * 3; i += 256) {
            int idx = base + i;
            float v = __ldcg(&out[idx]);
            #pragma unroll
            for (int c = 0; c < CHUNKS - 1; c++)
                v += __ldcg(&g_part[c * OUT_ELEMS + idx]);
            out[idx] = __frcp_rn(1.0f + __expf(-v * scl));
        }
    }
}

extern "C" void kernel_launch(void* const* d_in, const int* in_sizes, int n_in,
                              void* d_out, int out_size) {
    const float* mean  = (const float*)d_in[0];
    const float* alpha = (const float*)d_in[1];
    const float* scale = (const float*)d_in[2];
    const float* theta = (const float*)d_in[3];
    const float* rgb   = (const float*)d_in[4];
    float* out = (float*)d_out;

    splat_kernel<<<NBLK, 256>>>(out, mean, alpha, scale, theta, rgb);
}

// round 17
// speedup vs baseline: 1.2642x; 1.2642x over previous
#include <cuda_runtime.h>
#include <math_constants.h>

#define N_G      1500
#define CHUNKS   9
#define GPC      168                 // gaussians per chunk
#define PPC      84                  // pairs per chunk
#define N_G_PAD  (CHUNKS * GPC)      // 1512
#define HDIM     256
#define OUT_ELEMS (HDIM * HDIM * 3)
#define NBLK     (CHUNKS * 32)       // 288 splat blocks
#define BIAS     110.0f
#define UNSAFE_T 160.0f

__device__ float        g_part[(CHUNKS - 1) * OUT_ELEMS];
__device__ unsigned int g_qmax_bits = 0xFF800000u;  // -inf; RED.MIN-on-bits == float max (q<=0)

typedef unsigned long long u64;

__device__ __forceinline__ u64 f2add(u64 a, u64 b) {
    u64 r; asm("add.rn.f32x2 %0, %1, %2;" : "=l"(r) : "l"(a), "l"(b)); return r;
}
__device__ __forceinline__ u64 f2mul(u64 a, u64 b) {
    u64 r; asm("mul.rn.f32x2 %0, %1, %2;" : "=l"(r) : "l"(a), "l"(b)); return r;
}
__device__ __forceinline__ u64 f2fma(u64 a, u64 b, u64 c) {
    u64 r; asm("fma.rn.f32x2 %0, %1, %2, %3;" : "=l"(r) : "l"(a), "l"(b), "l"(c)); return r;
}
__device__ __forceinline__ u64 f2pack(float lo, float hi) {
    u64 r; asm("mov.b64 %0, {%1, %2};" : "=l"(r) : "f"(lo), "f"(hi)); return r;
}
__device__ __forceinline__ void f2unpack(u64 v, float& lo, float& hi) {
    asm("mov.b64 {%0, %1}, %2;" : "=f"(lo), "=f"(hi) : "l"(v));
}
__device__ __forceinline__ u64 f2ex2(u64 q) {
    float a, b; f2unpack(q, a, b);
    float wa, wb;
    asm("ex2.approx.ftz.f32 %0, %1;" : "=f"(wa) : "f"(a));
    asm("ex2.approx.ftz.f32 %0, %1;" : "=f"(wb) : "f"(b));
    return f2pack(wa, wb);
}
__device__ __forceinline__ float fast_tanh(float x) {
    float e = __expf(2.0f * x);
    return (e - 1.0f) * __frcp_rn(e + 1.0f);
}
__device__ __forceinline__ float fast_sigmoid(float x) {
    return __frcp_rn(1.0f + __expf(-x));
}

// R10 splat (best verified: 43.0us) + PDL trigger at the end.
// 288 blocks = 9 chunks x 32 rowblocks; 256 threads = 8 warps = 8 rows.
// In-block prep -> safe-first permutation -> qmax partials -> two uniform
// mainloops (geometric recurrence / additive-q), lane owns 8 contiguous px.
__global__ void __launch_bounds__(256, 2) splat_kernel(
    float* __restrict__ out,
    const float* __restrict__ mean, const float* __restrict__ alpha,
    const float* __restrict__ scale, const float* __restrict__ theta,
    const float* __restrict__ rgb)
{
    __shared__ __align__(16) float tmp[PPC * 24];
    __shared__ __align__(16) float sp[PPC * 24];
    __shared__ float          sflagg[GPC];
    __shared__ int            sperm[PPC];
    __shared__ int            snsafe;

    int tid    = threadIdx.x;
    int chunk  = blockIdx.x >> 5;
    int rowblk = blockIdx.x & 31;

    const float TWO_PI = 6.283185307179586f;
    const float K      = -0.7213475204444817f;   // -0.5*log2(e)
    const float STEP   = 2.0f / 255.0f;
    const float H      = 6.0f / 255.0f;

    // ---- in-block prep: this chunk's 168 gaussian params -> TEMP ----
    if (tid < GPC) {
        int g = chunk * GPC + tid;

        float A, B, C, mx, my, cr = 0.f, cg = 0.f, cb = 0.f;
        if (g < N_G) {
            float ang = fast_sigmoid(theta[g]) * TWO_PI;
            float s = __sinf(ang), c = __cosf(ang);
            float sx = scale[g * 2 + 0], sy = scale[g * 2 + 1];
            float sx2 = sx * sx, sy2 = sy * sy;

            float cov00 = c * c * sx2 + s * s * sy2 + 1e-6f;
            float cov01 = c * s * (sx2 - sy2);
            float cov11 = s * s * sx2 + c * c * sy2 + 1e-6f;

            float idet = __frcp_rn(cov00 * cov11 - cov01 * cov01);
            A = K * ( cov11 * idet);
            B = 2.0f * K * (-cov01 * idet);
            C = K * ( cov00 * idet);

            mx = fast_tanh(mean[g * 2 + 0]) * 3.0f;
            my = fast_tanh(mean[g * 2 + 1]) * 3.0f;

            float al = fast_sigmoid(alpha[g]);
            cr = (fast_tanh(rgb[g * 3 + 0]) * 2.0f + 1.0f) * 0.5f * al;
            cg = (fast_tanh(rgb[g * 3 + 1]) * 2.0f + 1.0f) * 0.5f * al;
            cb = (fast_tanh(rgb[g * 3 + 2]) * 2.0f + 1.0f) * 0.5f * al;
        } else {
            A = -1.f; B = 0.f; C = -1.f; mx = 0.f; my = 0.f;   // benign pad, zero color
        }

        int j = tid >> 1, o = tid & 1;
        float* p = &tmp[j * 24 + o];
        p[0]  = A;  p[2]  = B;  p[4]  = C;
        p[6]  = -mx; p[8] = -my;
        p[10] = 2.0f * A * H;              // P
        p[12] = A * H * H;                 // Q
        p[14] = B * H;                     // R
        p[16] = cr; p[18] = cg; p[20] = cb;
        p[22] = exp2f(2.0f * A * H * H);   // rho (A<0 -> <=1, finite)
        sflagg[tid] = (2.0f * fabsf(A) + fabsf(B) >= UNSAFE_T) ? 1.0f : 0.0f;
    }
    __syncthreads();

    // ---- deterministic safe-first permutation (thread 0, serial) ----
    if (tid == 0) {
        int ns = 0;
        for (int j = 0; j < PPC; j++)
            if (sflagg[2 * j] == 0.f && sflagg[2 * j + 1] == 0.f) ns++;
        int si = 0, ui = ns;
        for (int j = 0; j < PPC; j++) {
            bool safe = (sflagg[2 * j] == 0.f && sflagg[2 * j + 1] == 0.f);
            sperm[j] = safe ? si++ : ui++;
        }
        snsafe = ns;
    }
    __syncthreads();

    // ---- permute-copy TEMP -> SP ----
    {
        const u64* src = (const u64*)tmp;
        u64* dst = (u64*)sp;
        for (int i = tid; i < PPC * 12; i += 256) {
            int j = i / 12, w = i - j * 12;
            dst[sperm[j] * 12 + w] = src[i];
        }
    }
    __syncthreads();

    int warp = tid >> 5, lane = tid & 31;
    int row  = rowblk * 8 + warp;
    int x0i  = lane * 8;

    float py = (row * STEP - 1.0f) * 3.0f;
    float px = (x0i * STEP - 1.0f) * 3.0f;
    u64 py2   = f2pack(py, py);
    u64 px2   = f2pack(px, px);
    u64 BIAS2 = f2pack(BIAS, BIAS);
    int nsafe = snsafe;

    // ---- qmax partial: exact lattice row-max (TEMP order, pad-guarded) ----
    {
        float qbest = -CUDART_INF_F;
        #pragma unroll
        for (int i = lane; i < GPC; i += 32) {
            int g = chunk * GPC + i;
            if (g < N_G) {
                int j = i >> 1, o = i & 1;
                float A  = tmp[j * 24 + o + 0];
                float B  = tmp[j * 24 + o + 2];
                float Cc = tmp[j * 24 + o + 4];
                float mx = -tmp[j * 24 + o + 6];
                float my = -tmp[j * 24 + o + 8];
                float dy = py - my;
                float ct = Cc * dy * dy;
                float bd = B * dy;
                float xs = -B * 0.5f * __frcp_rn(A) * dy;      // continuous argmax
                float tt = fmaf(xs, 42.5f, 127.5f);
                float i0f = fminf(fmaxf(floorf(tt), 0.0f), 255.0f);
                float i1f = fminf(i0f + 1.0f, 255.0f);
                float x0 = (i0f * STEP - 1.0f) * 3.0f;
                float x1 = (i1f * STEP - 1.0f) * 3.0f;
                float d0 = x0 - mx, d1 = x1 - mx;
                float q0 = fmaf(fmaf(A, d0, bd), d0, ct);
                float q1 = fmaf(fmaf(A, d1, bd), d1, ct);
                qbest = fmaxf(qbest, fmaxf(q0, q1));
            }
        }
        #pragma unroll
        for (int off = 16; off > 0; off >>= 1)
            qbest = fmaxf(qbest, __shfl_xor_sync(0xFFFFFFFFu, qbest, off));
        if (lane == 0)
            atomicMin(&g_qmax_bits, __float_as_uint(qbest));
    }

    // ---- render: two uniform loops, lane owns 8 contiguous px ----
    u64 racc[8], gacc[8], bacc[8];
    #pragma unroll
    for (int k = 0; k < 8; k++) { racc[k] = 0ull; gacc[k] = 0ull; bacc[k] = 0ull; }

    const ulonglong2* spp = (const ulonglong2*)sp;

    // safe pairs: geometric recurrence (4 ex2 / pair-iter)
    for (int j = 0; j < nsafe; j++) {
        ulonglong2 p0 = spp[j * 6 + 0];  // {A, B}
        ulonglong2 p1 = spp[j * 6 + 1];  // {C, nmx}
        ulonglong2 p2 = spp[j * 6 + 2];  // {nmy, P}
        ulonglong2 p3 = spp[j * 6 + 3];  // {Q, R}
        ulonglong2 p4 = spp[j * 6 + 4];  // {cr, cg}
        ulonglong2 p5 = spp[j * 6 + 5];  // {cb, rho}

        u64 dy   = f2add(py2, p2.x);
        u64 dyq  = f2mul(dy, dy);
        u64 bdy  = f2mul(p0.y, dy);
        u64 cdyb = f2fma(p1.x, dyq, BIAS2);                  // C*dy^2 + BIAS
        u64 dx0  = f2add(px2, p1.y);
        u64 q0   = f2fma(f2fma(p0.x, dx0, bdy), dx0, cdyb);
        u64 e0   = f2fma(p2.y, dx0, f2fma(p3.y, dy, p3.x));  // P*dx0 + R*dy + Q

        u64 w = f2ex2(q0);
        u64 r = f2ex2(e0);
        #pragma unroll
        for (int k = 0; k < 8; k++) {
            racc[k] = f2fma(w, p4.x, racc[k]);
            gacc[k] = f2fma(w, p4.y, gacc[k]);
            bacc[k] = f2fma(w, p5.x, bacc[k]);
            w = f2mul(w, r);
            r = f2mul(r, p5.y);
        }
    }

    // unsafe pairs: additive-q chain (per-px ex2; flush-immune)
    for (int j = nsafe; j < PPC; j++) {
        ulonglong2 p0 = spp[j * 6 + 0];
        ulonglong2 p1 = spp[j * 6 + 1];
        ulonglong2 p2 = spp[j * 6 + 2];
        ulonglong2 p3 = spp[j * 6 + 3];
        ulonglong2 p4 = spp[j * 6 + 4];
        ulonglong2 p5 = spp[j * 6 + 5];

        u64 dy   = f2add(py2, p2.x);
        u64 dyq  = f2mul(dy, dy);
        u64 bdy  = f2mul(p0.y, dy);
        u64 cdyb = f2fma(p1.x, dyq, BIAS2);
        u64 dx0  = f2add(px2, p1.y);
        u64 q    = f2fma(f2fma(p0.x, dx0, bdy), dx0, cdyb);
        u64 e    = f2fma(p2.y, dx0, f2fma(p3.y, dy, p3.x));
        u64 t2   = f2add(p3.x, p3.x);                        // 2*A*h^2

        #pragma unroll
        for (int k = 0; k < 8; k++) {
            u64 w = f2ex2(q);
            racc[k] = f2fma(w, p4.x, racc[k]);
            gacc[k] = f2fma(w, p4.y, gacc[k]);
            bacc[k] = f2fma(w, p5.x, bacc[k]);
            q = f2add(q, e);
            e = f2add(e, t2);
        }
    }

    {
        float* dst = (chunk == 0) ? out : (g_part + (chunk - 1) * OUT_ELEMS);
        float* o = &dst[(row * HDIM + x0i) * 3];
        #pragma unroll
        for (int k = 0; k < 8; k++) {
            float t0, t1;
            f2unpack(racc[k], t0, t1); o[k * 3 + 0] = t0 + t1;
            f2unpack(gacc[k], t0, t1); o[k * 3 + 1] = t0 + t1;
            f2unpack(bacc[k], t0, t1); o[k * 3 + 2] = t0 + t1;
        }
    }

#if __CUDA_ARCH__ >= 900
    // PDL: allow the dependent finish kernel's blocks to launch now; its
    // cudaGridDependencySynchronize() still waits for ALL our memory to land.
    cudaTriggerProgrammaticLaunchCompletion();
#endif
}

// Scalar-grained finish: 1 thread per output float; 9 independent loads -> MLP.
// Launched with programmatic stream serialization: blocks spin up overlapped
// with splat's tail; the grid-dependency sync provides the ordering.
__global__ void __launch_bounds__(256) finish_kernel(float* __restrict__ out) {
#if __CUDA_ARCH__ >= 900
    cudaGridDependencySynchronize();
#endif
    int i = blockIdx.x * blockDim.x + threadIdx.x;
    if (i >= OUT_ELEMS) return;
    float qmax = __uint_as_float(g_qmax_bits);
    float scl  = exp2f(-qmax - BIAS);   // un-bias + 1/max(splat)

    float v = out[i];
    #pragma unroll
    for (int c = 0; c < CHUNKS - 1; c++)
        v += g_part[c * OUT_ELEMS + i];
    out[i] = __frcp_rn(1.0f + __expf(-v * scl));
}

extern "C" void kernel_launch(void* const* d_in, const int* in_sizes, int n_in,
                              void* d_out, int out_size) {
    const float* mean  = (const float*)d_in[0];
    const float* alpha = (const float*)d_in[1];
    const float* scale = (const float*)d_in[2];
    const float* theta = (const float*)d_in[3];
    const float* rgb   = (const float*)d_in[4];
    float* out = (float*)d_out;

    splat_kernel<<<NBLK, 256>>>(out, mean, alpha, scale, theta, rgb);

    // finish with programmatic dependent launch (overlap with splat tail)
    cudaLaunchConfig_t cfg = {};
    cfg.gridDim  = dim3((OUT_ELEMS + 255) / 256, 1, 1);
    cfg.blockDim = dim3(256, 1, 1);
    cfg.dynamicSmemBytes = 0;
    cfg.stream = 0;
    cudaLaunchAttribute attrs[1];
    attrs[0].id = cudaLaunchAttributeProgrammaticStreamSerialization;
    attrs[0].val.programmaticStreamSerializationAllowed = 1;
    cfg.attrs = attrs;
    cfg.numAttrs = 1;
    cudaLaunchKernelEx(&cfg, finish_kernel, out);
}